// round 6
// baseline (speedup 1.0000x reference)
#include <cuda_runtime.h>
#include <cuda_fp16.h>
#include <math.h>
#include <stdint.h>

#define LL 512
#define DS 256
#define HH 32
#define DP 128
#define KRBF 36

// ---------------- scratch globals ----------------
__device__ float    g_left[LL * HH];
__device__ float    g_right[LL * HH];      // [m][32] fp32
__device__ float    g_cas[LL * 4];
__device__ uint32_t g_tp_hi[LL * DP * 16]; // t^T fp16 hi: [l][p][16 words = 32 k]
__device__ uint32_t g_tp_lo[LL * DP * 16];
__device__ uint32_t g_wr_hi[DP * 24];      // w_rbf^T fp16 hi: [p][24 words = 48 k]
__device__ uint32_t g_wr_lo[DP * 24];

// ---------------- helpers ----------------
__device__ __forceinline__ uint32_t smem_u32(const void* p) {
    uint32_t a;
    asm("{ .reg .u64 t; cvta.to.shared.u64 t, %1; cvt.u32.u64 %0, t; }" : "=r"(a) : "l"(p));
    return a;
}
__device__ __forceinline__ uint32_t pk2(float a, float b) {
    __half2 h = __floats2half2_rn(a, b);
    return *(uint32_t*)&h;
}
__device__ __forceinline__ float hf(float x) {
    return __half2float(__float2half_rn(x));
}
__device__ __forceinline__ void mma16816(float d[4], const uint32_t a[4], const uint32_t b[2]) {
    asm volatile("mma.sync.aligned.m16n8k16.row.col.f32.f16.f16.f32 "
        "{%0,%1,%2,%3}, {%4,%5,%6,%7}, {%8,%9}, {%0,%1,%2,%3};"
        : "+f"(d[0]), "+f"(d[1]), "+f"(d[2]), "+f"(d[3])
        : "r"(a[0]), "r"(a[1]), "r"(a[2]), "r"(a[3]), "r"(b[0]), "r"(b[1]));
}
__device__ __forceinline__ void ldmx4(uint32_t r[4], uint32_t addr) {
    asm volatile("ldmatrix.sync.aligned.m8n8.x4.shared.b16 {%0,%1,%2,%3}, [%4];"
        : "=r"(r[0]), "=r"(r[1]), "=r"(r[2]), "=r"(r[3]) : "r"(addr));
}
__device__ __forceinline__ float sigmoidf_(float x) {
    return __fdividef(1.0f, 1.0f + __expf(-x));
}

// ---------------------------------------------------------------------------
// k_prep: 8 l per block. Warp-per-l LayerNorm, register-cached projection
// weights reused across the 8 l's. Block 0 also packs w_rbf^T and cas.
// grid = 64, 256 threads
// ---------------------------------------------------------------------------
__global__ __launch_bounds__(256) void k_prep(
    const float* __restrict__ xyz, const float* __restrict__ state,
    const float* __restrict__ ln_w, const float* __restrict__ ln_b,
    const float* __restrict__ w_left, const float* __restrict__ b_left,
    const float* __restrict__ w_right, const float* __restrict__ b_right,
    const float* __restrict__ w_rbf)
{
    __shared__ float st_s[8][DS];
    __shared__ float part[8][64][4];
    int lb = blockIdx.x * 8;
    int tid = threadIdx.x, lane = tid & 31, wid = tid >> 5;

    // ---- phase 1: warp `wid` does LayerNorm of l = lb + wid ----
    {
        int l = lb + wid;
        float4 v0 = *(const float4*)(state + l * DS + lane * 8);
        float4 v1 = *(const float4*)(state + l * DS + lane * 8 + 4);
        float s = v0.x + v0.y + v0.z + v0.w + v1.x + v1.y + v1.z + v1.w;
        float q = v0.x*v0.x + v0.y*v0.y + v0.z*v0.z + v0.w*v0.w
                + v1.x*v1.x + v1.y*v1.y + v1.z*v1.z + v1.w*v1.w;
        #pragma unroll
        for (int o = 16; o; o >>= 1) {
            s += __shfl_xor_sync(0xFFFFFFFFu, s, o);
            q += __shfl_xor_sync(0xFFFFFFFFu, q, o);
        }
        float mu = s * (1.0f / DS);
        float inv = rsqrtf(q * (1.0f / DS) - mu * mu + 1e-5f);
        float4 lw0 = *(const float4*)(ln_w + lane * 8);
        float4 lw1 = *(const float4*)(ln_w + lane * 8 + 4);
        float4 lb0 = *(const float4*)(ln_b + lane * 8);
        float4 lb1 = *(const float4*)(ln_b + lane * 8 + 4);
        float4 r0, r1;
        r0.x = (v0.x - mu) * inv * lw0.x + lb0.x;
        r0.y = (v0.y - mu) * inv * lw0.y + lb0.y;
        r0.z = (v0.z - mu) * inv * lw0.z + lb0.z;
        r0.w = (v0.w - mu) * inv * lw0.w + lb0.w;
        r1.x = (v1.x - mu) * inv * lw1.x + lb1.x;
        r1.y = (v1.y - mu) * inv * lw1.y + lb1.y;
        r1.z = (v1.z - mu) * inv * lw1.z + lb1.z;
        r1.w = (v1.w - mu) * inv * lw1.w + lb1.w;
        *(float4*)(&st_s[wid][lane * 8]) = r0;
        *(float4*)(&st_s[wid][lane * 8 + 4]) = r1;
    }
    __syncthreads();

    // ---- phase 2: projection, weights in registers, reused over 8 l ----
    {
        int j = tid & 31, half = (tid >> 5) & 1, seg = tid >> 6;
        const float* w = half ? w_right : w_left;
        float wreg[64];
        #pragma unroll 16
        for (int i = 0; i < 64; i++) wreg[i] = w[(seg * 64 + i) * HH + j];
        #pragma unroll
        for (int l8 = 0; l8 < 8; l8++) {
            float acc = 0.f;
            const float* ss = &st_s[l8][seg * 64];
            #pragma unroll 16
            for (int i = 0; i < 64; i++) acc += ss[i] * wreg[i];
            part[l8][half * 32 + j][seg] = acc;
        }
    }
    __syncthreads();

    // ---- combine partials ----
    #pragma unroll
    for (int it = 0; it < 2; it++) {
        int idx = it * 256 + tid;
        int l8 = idx >> 6, jj = idx & 63, j = jj & 31, half = jj >> 5;
        float4 pr = *(const float4*)(&part[l8][jj][0]);
        float a = pr.x + pr.y + pr.z + pr.w + (half ? b_right[j] : b_left[j]);
        if (half) g_right[(lb + l8) * HH + j] = a;
        else      g_left[(lb + l8) * HH + j] = a;
    }
    if (tid < 24) {
        int l8 = tid / 3, c = tid % 3;
        g_cas[(lb + l8) * 4 + c] = xyz[(lb + l8) * 9 + 3 + c];
    }
    // block 0: pack w_rbf^T fp16 hi/lo [p][48 k] (pad 36..47 = 0)
    if (blockIdx.x == 0 && tid < DP) {
        #pragma unroll
        for (int c = 0; c < 24; c++) {
            int k0 = 2 * c, k1 = 2 * c + 1;
            float v0 = (k0 < KRBF) ? w_rbf[k0 * DP + tid] : 0.f;
            float v1 = (k1 < KRBF) ? w_rbf[k1 * DP + tid] : 0.f;
            g_wr_hi[tid * 24 + c] = pk2(v0, v1);
            g_wr_lo[tid * 24 + c] = pk2(v0 - hf(v0), v1 - hf(v1));
        }
    }
}

// ---------------------------------------------------------------------------
// k_t: t[l,k,p] = sum_i left[l,i]*Wg[i,k,p]; emit t^T fp16 hi/lo [l][p][k]
// grid = (64 lb, 8 jb): 8 l x 4 j x 128 p per block, 128 threads
// ---------------------------------------------------------------------------
__global__ __launch_bounds__(128) void k_t(const float* __restrict__ w_gate)
{
    __shared__ float ls[8 * HH];
    int lb = blockIdx.x * 8, j0 = blockIdx.y * 4, p = threadIdx.x;
    for (int i = p; i < 8 * HH; i += 128) ls[i] = g_left[lb * HH + i];
    __syncthreads();

    float acc[8][4];
    #pragma unroll
    for (int lt = 0; lt < 8; lt++)
        #pragma unroll
        for (int qj = 0; qj < 4; qj++) acc[lt][qj] = 0.f;

    #pragma unroll 4
    for (int i = 0; i < HH; i++) {
        float wv[4];
        #pragma unroll
        for (int qj = 0; qj < 4; qj++)
            wv[qj] = w_gate[(i * HH + j0 + qj) * DP + p];
        #pragma unroll
        for (int lt = 0; lt < 8; lt++) {
            float lv = ls[lt * HH + i];
            #pragma unroll
            for (int qj = 0; qj < 4; qj++) acc[lt][qj] += lv * wv[qj];
        }
    }
    int c0 = j0 >> 1;   // word index (2 words per block)
    #pragma unroll
    for (int lt = 0; lt < 8; lt++) {
        uint32_t h0 = pk2(acc[lt][0], acc[lt][1]);
        uint32_t h1 = pk2(acc[lt][2], acc[lt][3]);
        uint32_t l0 = pk2(acc[lt][0] - hf(acc[lt][0]), acc[lt][1] - hf(acc[lt][1]));
        uint32_t l1 = pk2(acc[lt][2] - hf(acc[lt][2]), acc[lt][3] - hf(acc[lt][3]));
        uint32_t base = (uint32_t)((lb + lt) * DP + p) * 16u + c0;
        *(uint2*)(g_tp_hi + base) = make_uint2(h0, h1);
        *(uint2*)(g_tp_lo + base) = make_uint2(l0, l1);
    }
}

// ---------------------------------------------------------------------------
// k_main: mma.sync fp16 2-product split. Block = (l, 128 m) x 128 p, 16 warps.
// Warp tile 32m x 32p: M0 = (wid&3)*32, P0 = (wid>>2)*32.
// A (m-side, hi only): A1 = right [128][80B], A2 = rbf [128][112B]
// B (p-side, hi+lo):   B1 = t^T [128][80B], B2 = wrbf^T [128][112B]
// Epilogue staged through per-warp smem (36-word rows, 16B-aligned) for
// full-line STG.128.
// ---------------------------------------------------------------------------
#define A1H 0
#define A2H 10240
#define B1H 24576
#define B1L 34816
#define B2H 45056
#define B2L 59392
#define STG0 73728
#define STG_ROW 36         // words per staging row (144 B, 16B-aligned)
#define STG_WARP (32 * STG_ROW * 4)   // 4608 B
#define SMTOT (73728 + 16 * STG_WARP) // 147456 B

__global__ __launch_bounds__(512) void k_main(
    const float* __restrict__ b_rbf, const float* __restrict__ b_gate,
    float* __restrict__ out)
{
    extern __shared__ char smem[];
    __shared__ float dist_s[128];
    uint32_t sb = smem_u32(smem);
    int tid = threadIdx.x, lane = tid & 31, wid = tid >> 5;
    int l = blockIdx.x, mb = blockIdx.y * 128;

    if (tid < 128) {
        int m = mb + tid;
        float dx = g_cas[m * 4]     - g_cas[l * 4];
        float dy = g_cas[m * 4 + 1] - g_cas[l * 4 + 1];
        float dz = g_cas[m * 4 + 2] - g_cas[l * 4 + 2];
        dist_s[tid] = sqrtf(fmaxf(dx * dx + dy * dy + dz * dz, 1e-12f));
    }

    // A1 fill: right -> fp16 hi [128][80B]
    {
        int row = tid >> 2, ch = tid & 3;
        const float4* src = (const float4*)(g_right + (mb + row) * HH + ch * 8);
        float4 x = src[0], y = src[1];
        uint4 h = make_uint4(pk2(x.x, x.y), pk2(x.z, x.w), pk2(y.x, y.y), pk2(y.z, y.w));
        *(uint4*)(smem + A1H + row * 80 + ch * 16) = h;
    }
    // B1 fill: t^T hi/lo [128][80B]
    {
        int row = tid >> 2, ch = tid & 3;
        uint32_t gb = (uint32_t)(l * DP + row) * 16u + ch * 4;
        *(uint4*)(smem + B1H + row * 80 + ch * 16) = *(const uint4*)(g_tp_hi + gb);
        *(uint4*)(smem + B1L + row * 80 + ch * 16) = *(const uint4*)(g_tp_lo + gb);
    }
    // B2 fill: w_rbf^T hi/lo [128][112B] (768 chunks)
    #pragma unroll
    for (int it = 0; it < 2; it++) {
        int idx = it * 512 + tid;
        if (idx < 768) {
            int row = idx / 6, ch = idx - row * 6;
            *(uint4*)(smem + B2H + row * 112 + ch * 16) = *(const uint4*)(g_wr_hi + row * 24 + ch * 4);
            *(uint4*)(smem + B2L + row * 112 + ch * 16) = *(const uint4*)(g_wr_lo + row * 24 + ch * 4);
        }
    }
    __syncthreads();

    // A2 fill: rbf features fp16 hi [128][112B]
    {
        int m = tid >> 2, kg = tid & 3;
        float dist = dist_s[m];
        const float DMU = 20.0f / 35.0f, INV_SIG = 36.0f / 20.0f;
        #pragma unroll
        for (int kk = 0; kk < 6; kk++) {
            int k = kg * 12 + 2 * kk;
            float e0 = 0.f, e1 = 0.f;
            if (k < KRBF) {
                float u = (dist - (2.0f + (float)k * DMU)) * INV_SIG;
                e0 = __expf(-u * u);
            }
            if (k + 1 < KRBF) {
                float u = (dist - (2.0f + (float)(k + 1) * DMU)) * INV_SIG;
                e1 = __expf(-u * u);
            }
            *(uint32_t*)(smem + A2H + m * 112 + k * 2) = pk2(e0, e1);
        }
    }
    __syncthreads();

    // ---- ldmatrix address components ----
    uint32_t rr = lane & 7, q = lane >> 3;
    uint32_t a_r = (q & 1) << 3, a_k = (q >> 1) << 3;
    uint32_t b_r = (q >> 1) << 3, b_k = (q & 1) << 3;
    int M0 = (wid & 3) * 32, P0 = (wid >> 2) * 32;

    // ---- pass 1: logits (K=32, 2 ks) ----
    uint32_t Ah[2][2][4];
    #pragma unroll
    for (int mt = 0; mt < 2; mt++)
        #pragma unroll
        for (int ks = 0; ks < 2; ks++)
            ldmx4(Ah[mt][ks], sb + A1H + (M0 + mt * 16 + rr + a_r) * 80 + (ks * 16 + a_k) * 2);

    float accL[2][4][4];
    #pragma unroll
    for (int mt = 0; mt < 2; mt++)
        #pragma unroll
        for (int nt = 0; nt < 4; nt++)
            #pragma unroll
            for (int j = 0; j < 4; j++) accL[mt][nt][j] = 0.f;

    #pragma unroll
    for (int npp = 0; npp < 2; npp++) {
        int n0 = P0 + npp * 16;
        uint32_t bbase = sb + B1H + (n0 + rr + b_r) * 80 + b_k * 2;
        #pragma unroll
        for (int ks = 0; ks < 2; ks++) {
            uint32_t bh[4], bl[4];
            ldmx4(bh, bbase + ks * 32);
            ldmx4(bl, bbase + ks * 32 + (B1L - B1H));
            #pragma unroll
            for (int mt = 0; mt < 2; mt++) {
                mma16816(accL[mt][2 * npp],     Ah[mt][ks], bh);
                mma16816(accL[mt][2 * npp],     Ah[mt][ks], bl);
                mma16816(accL[mt][2 * npp + 1], Ah[mt][ks], bh + 2);
                mma16816(accL[mt][2 * npp + 1], Ah[mt][ks], bl + 2);
            }
        }
    }

    // ---- pass 2: feat (K=48, 3 ks) + epilogue into staging ----
    uint32_t Fh[2][3][4];
    #pragma unroll
    for (int mt = 0; mt < 2; mt++)
        #pragma unroll
        for (int ks = 0; ks < 3; ks++)
            ldmx4(Fh[mt][ks], sb + A2H + (M0 + mt * 16 + rr + a_r) * 112 + (ks * 16 + a_k) * 2);

    int r0 = lane >> 2, c2 = (lane & 3) * 2;
    float* stg = (float*)(smem + STG0 + wid * STG_WARP);

    #pragma unroll
    for (int npp = 0; npp < 2; npp++) {
        int n0 = P0 + npp * 16;
        uint32_t bbase = sb + B2H + (n0 + rr + b_r) * 112 + b_k * 2;
        float accF[2][2][4];
        #pragma unroll
        for (int mt = 0; mt < 2; mt++)
            #pragma unroll
            for (int nt = 0; nt < 2; nt++)
                #pragma unroll
                for (int j = 0; j < 4; j++) accF[mt][nt][j] = 0.f;
        #pragma unroll
        for (int ks = 0; ks < 3; ks++) {
            uint32_t bh[4], bl[4];
            ldmx4(bh, bbase + ks * 32);
            ldmx4(bl, bbase + ks * 32 + (B2L - B2H));
            #pragma unroll
            for (int mt = 0; mt < 2; mt++) {
                mma16816(accF[mt][0], Fh[mt][ks], bh);
                mma16816(accF[mt][0], Fh[mt][ks], bl);
                mma16816(accF[mt][1], Fh[mt][ks], bh + 2);
                mma16816(accF[mt][1], Fh[mt][ks], bl + 2);
            }
        }
        // epilogue -> staging smem
        #pragma unroll
        for (int mt = 0; mt < 2; mt++) {
            #pragma unroll
            for (int ntl = 0; ntl < 2; ntl++) {
                int pl = npp * 16 + ntl * 8 + c2;
                int pg = P0 + pl;
                float2 bg = *(const float2*)(b_gate + pg);
                float2 br = *(const float2*)(b_rbf + pg);
                const float* Lc = accL[mt][2 * npp + ntl];
                const float* Fc = accF[mt][ntl];
                int ra = mt * 16 + r0;
                float2 v0, v1;
                v0.x = (Fc[0] + br.x) * sigmoidf_(Lc[0] + bg.x);
                v0.y = (Fc[1] + br.y) * sigmoidf_(Lc[1] + bg.y);
                v1.x = (Fc[2] + br.x) * sigmoidf_(Lc[2] + bg.x);
                v1.y = (Fc[3] + br.y) * sigmoidf_(Lc[3] + bg.y);
                *(float2*)(stg + ra * STG_ROW + pl) = v0;
                *(float2*)(stg + (ra + 8) * STG_ROW + pl) = v1;
            }
        }
    }
    __syncwarp();

    // ---- drain: 4 rows per STG.128, full 128B lines ----
    {
        int c4 = lane & 7, rq = lane >> 3;
        #pragma unroll
        for (int it = 0; it < 8; it++) {
            int rs = it * 4 + rq;
            float4 v = *(const float4*)(stg + rs * STG_ROW + c4 * 4);
            int m = mb + M0 + rs;
            *(float4*)(out + ((size_t)l * LL + m) * DP + P0 + c4 * 4) = v;
        }
    }
}

// ---------------------------------------------------------------------------
extern "C" void kernel_launch(void* const* d_in, const int* in_sizes, int n_in,
                              void* d_out, int out_size)
{
    const float* xyz     = (const float*)d_in[0];
    const float* state   = (const float*)d_in[1];
    const float* ln_w    = (const float*)d_in[2];
    const float* ln_b    = (const float*)d_in[3];
    const float* w_rbf   = (const float*)d_in[4];
    const float* b_rbf   = (const float*)d_in[5];
    const float* w_left  = (const float*)d_in[6];
    const float* b_left  = (const float*)d_in[7];
    const float* w_right = (const float*)d_in[8];
    const float* b_right = (const float*)d_in[9];
    const float* w_gate  = (const float*)d_in[10];
    const float* b_gate  = (const float*)d_in[11];
    float* out = (float*)d_out;

    k_prep<<<64, 256>>>(xyz, state, ln_w, ln_b, w_left, b_left, w_right, b_right, w_rbf);
    k_t<<<dim3(64, 8), 128>>>(w_gate);

    cudaFuncSetAttribute(k_main, cudaFuncAttributeMaxDynamicSharedMemorySize, SMTOT);
    k_main<<<dim3(LL, 4), 512, SMTOT>>>(b_rbf, b_gate, out);
}

// round 7
// speedup vs baseline: 1.0589x; 1.0589x over previous
#include <cuda_runtime.h>
#include <cuda_fp16.h>
#include <math.h>
#include <stdint.h>

#define LL 512
#define DS 256
#define HH 32
#define DP 128
#define KRBF 36

// ---------------- scratch globals ----------------
__device__ float    g_left[LL * HH];
__device__ float    g_right[LL * HH];      // [m][32] fp32
__device__ float    g_cas[LL * 4];
__device__ uint32_t g_tp_hi[LL * DP * 16]; // t^T fp16 hi: [l][p][16 words = 32 k]
__device__ uint32_t g_tp_lo[LL * DP * 16];
__device__ uint32_t g_wr_hi[DP * 24];      // w_rbf^T fp16 hi: [p][24 words = 48 k]
__device__ uint32_t g_wr_lo[DP * 24];

// ---------------- helpers ----------------
__device__ __forceinline__ uint32_t smem_u32(const void* p) {
    uint32_t a;
    asm("{ .reg .u64 t; cvta.to.shared.u64 t, %1; cvt.u32.u64 %0, t; }" : "=r"(a) : "l"(p));
    return a;
}
__device__ __forceinline__ uint32_t pk2(float a, float b) {
    __half2 h = __floats2half2_rn(a, b);
    return *(uint32_t*)&h;
}
__device__ __forceinline__ float hf(float x) {
    return __half2float(__float2half_rn(x));
}
__device__ __forceinline__ void mma16816(float d[4], const uint32_t a[4], const uint32_t b[2]) {
    asm volatile("mma.sync.aligned.m16n8k16.row.col.f32.f16.f16.f32 "
        "{%0,%1,%2,%3}, {%4,%5,%6,%7}, {%8,%9}, {%0,%1,%2,%3};"
        : "+f"(d[0]), "+f"(d[1]), "+f"(d[2]), "+f"(d[3])
        : "r"(a[0]), "r"(a[1]), "r"(a[2]), "r"(a[3]), "r"(b[0]), "r"(b[1]));
}
__device__ __forceinline__ void ldmx4(uint32_t r[4], uint32_t addr) {
    asm volatile("ldmatrix.sync.aligned.m8n8.x4.shared.b16 {%0,%1,%2,%3}, [%4];"
        : "=r"(r[0]), "=r"(r[1]), "=r"(r[2]), "=r"(r[3]) : "r"(addr));
}
__device__ __forceinline__ float sigmoidf_(float x) {
    return __fdividef(1.0f, 1.0f + __expf(-x));
}

// ---------------------------------------------------------------------------
// k_prep: 2 l per block (grid 256) — halves weight traffic vs 1-l blocks
// while keeping high block-level parallelism. 128 threads per l for LN.
// Block 0 also packs w_rbf^T.
// ---------------------------------------------------------------------------
__global__ __launch_bounds__(256) void k_prep(
    const float* __restrict__ xyz, const float* __restrict__ state,
    const float* __restrict__ ln_w, const float* __restrict__ ln_b,
    const float* __restrict__ w_left, const float* __restrict__ b_left,
    const float* __restrict__ w_right, const float* __restrict__ b_right,
    const float* __restrict__ w_rbf)
{
    __shared__ float st_s[2][DS];
    __shared__ float redw[8], redq[8];
    __shared__ float part[2][64][2];
    int tid = threadIdx.x, lane = tid & 31, wid = tid >> 5;
    int l2 = tid >> 7, lt = tid & 127;
    int l = blockIdx.x * 2 + l2;

    // ---- LayerNorm: 128 threads per l, 2 elements each ----
    float2 v = *(const float2*)(state + l * DS + lt * 2);
    {
        float s = v.x + v.y, q = v.x * v.x + v.y * v.y;
        #pragma unroll
        for (int o = 16; o; o >>= 1) {
            s += __shfl_xor_sync(0xFFFFFFFFu, s, o);
            q += __shfl_xor_sync(0xFFFFFFFFu, q, o);
        }
        if (lane == 0) { redw[wid] = s; redq[wid] = q; }
    }
    __syncthreads();
    {
        int b0 = l2 * 4;
        float S = redw[b0] + redw[b0 + 1] + redw[b0 + 2] + redw[b0 + 3];
        float Q = redq[b0] + redq[b0 + 1] + redq[b0 + 2] + redq[b0 + 3];
        float mu = S * (1.0f / DS);
        float inv = rsqrtf(Q * (1.0f / DS) - mu * mu + 1e-5f);
        float2 lw = *(const float2*)(ln_w + lt * 2);
        float2 lbv = *(const float2*)(ln_b + lt * 2);
        float2 r;
        r.x = (v.x - mu) * inv * lw.x + lbv.x;
        r.y = (v.y - mu) * inv * lw.y + lbv.y;
        *(float2*)(&st_s[l2][lt * 2]) = r;
    }
    __syncthreads();

    // ---- projection: 256 tasks = (l2, half, seg, j), 128-FMA dots ----
    {
        int j = tid & 31, seg = (tid >> 5) & 1, half = (tid >> 6) & 1, lp = tid >> 7;
        const float* w = half ? w_right : w_left;
        const float* ss = &st_s[lp][seg * 128];
        const float* wp = w + seg * 128 * HH + j;
        float acc = 0.f;
        #pragma unroll 16
        for (int i = 0; i < 128; i++) acc += ss[i] * wp[i * HH];
        part[lp][half * 32 + j][seg] = acc;
    }
    __syncthreads();
    if (tid < 128) {
        int lp = tid >> 6, jj = tid & 63, j = jj & 31, half = jj >> 5;
        float a = part[lp][jj][0] + part[lp][jj][1] + (half ? b_right[j] : b_left[j]);
        if (half) g_right[(blockIdx.x * 2 + lp) * HH + j] = a;
        else      g_left[(blockIdx.x * 2 + lp) * HH + j] = a;
    }
    if (tid < 6) {
        int lp = tid / 3, c = tid % 3;
        g_cas[(blockIdx.x * 2 + lp) * 4 + c] = xyz[(blockIdx.x * 2 + lp) * 9 + 3 + c];
    }
    if (blockIdx.x == 0 && tid < DP) {
        #pragma unroll
        for (int c = 0; c < 24; c++) {
            int k0 = 2 * c, k1 = 2 * c + 1;
            float v0 = (k0 < KRBF) ? w_rbf[k0 * DP + tid] : 0.f;
            float v1 = (k1 < KRBF) ? w_rbf[k1 * DP + tid] : 0.f;
            g_wr_hi[tid * 24 + c] = pk2(v0, v1);
            g_wr_lo[tid * 24 + c] = pk2(v0 - hf(v0), v1 - hf(v1));
        }
    }
}

// ---------------------------------------------------------------------------
// k_t: t[l,k,p] = sum_i left[l,i]*Wg[i,k,p]; emit t^T fp16 hi/lo [l][p][k]
// grid = (64 lb, 8 jb): 8 l x 4 j x 128 p per block, 128 threads
// ---------------------------------------------------------------------------
__global__ __launch_bounds__(128) void k_t(const float* __restrict__ w_gate)
{
    __shared__ float ls[8 * HH];
    int lb = blockIdx.x * 8, j0 = blockIdx.y * 4, p = threadIdx.x;
    for (int i = p; i < 8 * HH; i += 128) ls[i] = g_left[lb * HH + i];
    __syncthreads();

    float acc[8][4];
    #pragma unroll
    for (int lt = 0; lt < 8; lt++)
        #pragma unroll
        for (int qj = 0; qj < 4; qj++) acc[lt][qj] = 0.f;

    #pragma unroll 4
    for (int i = 0; i < HH; i++) {
        float wv[4];
        #pragma unroll
        for (int qj = 0; qj < 4; qj++)
            wv[qj] = w_gate[(i * HH + j0 + qj) * DP + p];
        #pragma unroll
        for (int lt = 0; lt < 8; lt++) {
            float lv = ls[lt * HH + i];
            #pragma unroll
            for (int qj = 0; qj < 4; qj++) acc[lt][qj] += lv * wv[qj];
        }
    }
    int c0 = j0 >> 1;
    #pragma unroll
    for (int lt = 0; lt < 8; lt++) {
        uint32_t h0 = pk2(acc[lt][0], acc[lt][1]);
        uint32_t h1 = pk2(acc[lt][2], acc[lt][3]);
        uint32_t l0 = pk2(acc[lt][0] - hf(acc[lt][0]), acc[lt][1] - hf(acc[lt][1]));
        uint32_t l1 = pk2(acc[lt][2] - hf(acc[lt][2]), acc[lt][3] - hf(acc[lt][3]));
        uint32_t base = (uint32_t)((lb + lt) * DP + p) * 16u + c0;
        *(uint2*)(g_tp_hi + base) = make_uint2(h0, h1);
        *(uint2*)(g_tp_lo + base) = make_uint2(l0, l1);
    }
}

// ---------------------------------------------------------------------------
// k_main: R4 structure (64-m tile, 256 thr, 2 blocks/SM) + staged epilogue.
// Warp tile 32m x 32p: M0 = (wid&1)*32, P0 = (wid>>1)*32.
// Staging: 36-word rows (144B, 16B-aligned); drain = full-line STG.128.
// ---------------------------------------------------------------------------
#define A1H 0
#define A2H 5120
#define B1H 12288
#define B1L 22528
#define B2H 32768
#define B2L 47104
#define STG0 61440
#define STG_ROW 36
#define STG_WARP (32 * STG_ROW * 4)     // 4608 B
#define SMTOT (61440 + 8 * STG_WARP)    // 98304 B -> 2 blocks/SM

__global__ __launch_bounds__(256) void k_main(
    const float* __restrict__ b_rbf, const float* __restrict__ b_gate,
    float* __restrict__ out)
{
    extern __shared__ char smem[];
    __shared__ float dist_s[64];
    uint32_t sb = smem_u32(smem);
    int tid = threadIdx.x, lane = tid & 31, wid = tid >> 5;
    int l = blockIdx.x, mb = blockIdx.y * 64;

    if (tid < 64) {
        int m = mb + tid;
        float dx = g_cas[m * 4]     - g_cas[l * 4];
        float dy = g_cas[m * 4 + 1] - g_cas[l * 4 + 1];
        float dz = g_cas[m * 4 + 2] - g_cas[l * 4 + 2];
        dist_s[tid] = sqrtf(fmaxf(dx * dx + dy * dy + dz * dz, 1e-12f));
    }

    // A1 fill: right -> fp16 hi [64][80B]
    {
        int row = tid >> 2, ch = tid & 3;
        const float4* src = (const float4*)(g_right + (mb + row) * HH + ch * 8);
        float4 x = src[0], y = src[1];
        uint4 h = make_uint4(pk2(x.x, x.y), pk2(x.z, x.w), pk2(y.x, y.y), pk2(y.z, y.w));
        *(uint4*)(smem + A1H + row * 80 + ch * 16) = h;
    }
    // B1 fill: t^T hi/lo [128][80B]
    #pragma unroll
    for (int it = 0; it < 2; it++) {
        int idx = it * 256 + tid;
        int row = idx >> 2, ch = idx & 3;
        uint32_t gb = (uint32_t)(l * DP + row) * 16u + ch * 4;
        *(uint4*)(smem + B1H + row * 80 + ch * 16) = *(const uint4*)(g_tp_hi + gb);
        *(uint4*)(smem + B1L + row * 80 + ch * 16) = *(const uint4*)(g_tp_lo + gb);
    }
    // B2 fill: w_rbf^T hi/lo [128][112B]
    #pragma unroll
    for (int it = 0; it < 3; it++) {
        int idx = it * 256 + tid;
        int row = idx / 6, ch = idx - row * 6;
        *(uint4*)(smem + B2H + row * 112 + ch * 16) = *(const uint4*)(g_wr_hi + row * 24 + ch * 4);
        *(uint4*)(smem + B2L + row * 112 + ch * 16) = *(const uint4*)(g_wr_lo + row * 24 + ch * 4);
    }
    __syncthreads();

    // A2 fill: rbf features fp16 hi [64][112B]
    {
        int m = tid >> 2, kg = tid & 3;
        float dist = dist_s[m];
        const float DMU = 20.0f / 35.0f, INV_SIG = 36.0f / 20.0f;
        #pragma unroll
        for (int kk = 0; kk < 6; kk++) {
            int k = kg * 12 + 2 * kk;
            float e0 = 0.f, e1 = 0.f;
            if (k < KRBF) {
                float u = (dist - (2.0f + (float)k * DMU)) * INV_SIG;
                e0 = __expf(-u * u);
            }
            if (k + 1 < KRBF) {
                float u = (dist - (2.0f + (float)(k + 1) * DMU)) * INV_SIG;
                e1 = __expf(-u * u);
            }
            *(uint32_t*)(smem + A2H + m * 112 + k * 2) = pk2(e0, e1);
        }
    }
    __syncthreads();

    // ---- ldmatrix address components ----
    uint32_t rr = lane & 7, q = lane >> 3;
    uint32_t a_r = (q & 1) << 3, a_k = (q >> 1) << 3;
    uint32_t b_r = (q >> 1) << 3, b_k = (q & 1) << 3;
    int M0 = (wid & 1) * 32, P0 = (wid >> 1) * 32;

    // ---- pass 1: logits (K=32, 2 ks) ----
    uint32_t Ah[2][2][4];
    #pragma unroll
    for (int mt = 0; mt < 2; mt++)
        #pragma unroll
        for (int ks = 0; ks < 2; ks++)
            ldmx4(Ah[mt][ks], sb + A1H + (M0 + mt * 16 + rr + a_r) * 80 + (ks * 16 + a_k) * 2);

    float accL[2][4][4];
    #pragma unroll
    for (int mt = 0; mt < 2; mt++)
        #pragma unroll
        for (int nt = 0; nt < 4; nt++)
            #pragma unroll
            for (int j = 0; j < 4; j++) accL[mt][nt][j] = 0.f;

    #pragma unroll
    for (int npp = 0; npp < 2; npp++) {
        int n0 = P0 + npp * 16;
        uint32_t bbase = sb + B1H + (n0 + rr + b_r) * 80 + b_k * 2;
        #pragma unroll
        for (int ks = 0; ks < 2; ks++) {
            uint32_t bh[4], bl[4];
            ldmx4(bh, bbase + ks * 32);
            ldmx4(bl, bbase + ks * 32 + (B1L - B1H));
            #pragma unroll
            for (int mt = 0; mt < 2; mt++) {
                mma16816(accL[mt][2 * npp],     Ah[mt][ks], bh);
                mma16816(accL[mt][2 * npp],     Ah[mt][ks], bl);
                mma16816(accL[mt][2 * npp + 1], Ah[mt][ks], bh + 2);
                mma16816(accL[mt][2 * npp + 1], Ah[mt][ks], bl + 2);
            }
        }
    }

    // ---- pass 2: feat (K=48, 3 ks) + epilogue into staging ----
    uint32_t Fh[2][3][4];
    #pragma unroll
    for (int mt = 0; mt < 2; mt++)
        #pragma unroll
        for (int ks = 0; ks < 3; ks++)
            ldmx4(Fh[mt][ks], sb + A2H + (M0 + mt * 16 + rr + a_r) * 112 + (ks * 16 + a_k) * 2);

    int r0 = lane >> 2, c2 = (lane & 3) * 2;
    float* stg = (float*)(smem + STG0 + wid * STG_WARP);

    #pragma unroll
    for (int npp = 0; npp < 2; npp++) {
        int n0 = P0 + npp * 16;
        uint32_t bbase = sb + B2H + (n0 + rr + b_r) * 112 + b_k * 2;
        float accF[2][2][4];
        #pragma unroll
        for (int mt = 0; mt < 2; mt++)
            #pragma unroll
            for (int nt = 0; nt < 2; nt++)
                #pragma unroll
                for (int j = 0; j < 4; j++) accF[mt][nt][j] = 0.f;
        #pragma unroll
        for (int ks = 0; ks < 3; ks++) {
            uint32_t bh[4], bl[4];
            ldmx4(bh, bbase + ks * 32);
            ldmx4(bl, bbase + ks * 32 + (B2L - B2H));
            #pragma unroll
            for (int mt = 0; mt < 2; mt++) {
                mma16816(accF[mt][0], Fh[mt][ks], bh);
                mma16816(accF[mt][0], Fh[mt][ks], bl);
                mma16816(accF[mt][1], Fh[mt][ks], bh + 2);
                mma16816(accF[mt][1], Fh[mt][ks], bl + 2);
            }
        }
        // epilogue -> per-warp staging smem
        #pragma unroll
        for (int mt = 0; mt < 2; mt++) {
            #pragma unroll
            for (int ntl = 0; ntl < 2; ntl++) {
                int pl = npp * 16 + ntl * 8 + c2;
                int pg = P0 + pl;
                float2 bg = *(const float2*)(b_gate + pg);
                float2 br = *(const float2*)(b_rbf + pg);
                const float* Lc = accL[mt][2 * npp + ntl];
                const float* Fc = accF[mt][ntl];
                int ra = mt * 16 + r0;
                float2 v0, v1;
                v0.x = (Fc[0] + br.x) * sigmoidf_(Lc[0] + bg.x);
                v0.y = (Fc[1] + br.y) * sigmoidf_(Lc[1] + bg.y);
                v1.x = (Fc[2] + br.x) * sigmoidf_(Lc[2] + bg.x);
                v1.y = (Fc[3] + br.y) * sigmoidf_(Lc[3] + bg.y);
                *(float2*)(stg + ra * STG_ROW + pl) = v0;
                *(float2*)(stg + (ra + 8) * STG_ROW + pl) = v1;
            }
        }
    }
    __syncwarp();

    // ---- drain: 4 rows per STG.128, full 128B lines ----
    {
        int c4 = lane & 7, rq = lane >> 3;
        #pragma unroll
        for (int it = 0; it < 8; it++) {
            int rs = it * 4 + rq;
            float4 vv = *(const float4*)(stg + rs * STG_ROW + c4 * 4);
            int m = mb + M0 + rs;
            *(float4*)(out + ((size_t)l * LL + m) * DP + P0 + c4 * 4) = vv;
        }
    }
}

// ---------------------------------------------------------------------------
extern "C" void kernel_launch(void* const* d_in, const int* in_sizes, int n_in,
                              void* d_out, int out_size)
{
    const float* xyz     = (const float*)d_in[0];
    const float* state   = (const float*)d_in[1];
    const float* ln_w    = (const float*)d_in[2];
    const float* ln_b    = (const float*)d_in[3];
    const float* w_rbf   = (const float*)d_in[4];
    const float* b_rbf   = (const float*)d_in[5];
    const float* w_left  = (const float*)d_in[6];
    const float* b_left  = (const float*)d_in[7];
    const float* w_right = (const float*)d_in[8];
    const float* b_right = (const float*)d_in[9];
    const float* w_gate  = (const float*)d_in[10];
    const float* b_gate  = (const float*)d_in[11];
    float* out = (float*)d_out;

    k_prep<<<256, 256>>>(xyz, state, ln_w, ln_b, w_left, b_left, w_right, b_right, w_rbf);
    k_t<<<dim3(64, 8), 128>>>(w_gate);

    cudaFuncSetAttribute(k_main, cudaFuncAttributeMaxDynamicSharedMemorySize, SMTOT);
    k_main<<<dim3(LL, 8), 256, SMTOT>>>(b_rbf, b_gate, out);
}

// round 11
// speedup vs baseline: 1.1240x; 1.0615x over previous
#include <cuda_runtime.h>
#include <cuda_fp16.h>
#include <math.h>
#include <stdint.h>

#define LL 512
#define DS 256
#define HH 32
#define DP 128
#define KRBF 36

// ---------------- scratch globals ----------------
__device__ float    g_right[LL * HH];      // [m][32] fp32
__device__ float    g_cas[LL * 4];
__device__ uint32_t g_tp[LL * DP * 16];    // t^T fp16: [l][p][16 words = 32 k]
__device__ uint32_t g_wr[DP * 24];         // w_rbf^T fp16: [p][24 words = 48 k]

// ---------------- helpers ----------------
__device__ __forceinline__ uint32_t smem_u32(const void* p) {
    uint32_t a;
    asm("{ .reg .u64 t; cvta.to.shared.u64 t, %1; cvt.u32.u64 %0, t; }" : "=r"(a) : "l"(p));
    return a;
}
__device__ __forceinline__ uint32_t pk2(float a, float b) {
    __half2 h = __floats2half2_rn(a, b);
    return *(uint32_t*)&h;
}
__device__ __forceinline__ void mma16816(float d[4], const uint32_t a[4], const uint32_t b[2]) {
    asm volatile("mma.sync.aligned.m16n8k16.row.col.f32.f16.f16.f32 "
        "{%0,%1,%2,%3}, {%4,%5,%6,%7}, {%8,%9}, {%0,%1,%2,%3};"
        : "+f"(d[0]), "+f"(d[1]), "+f"(d[2]), "+f"(d[3])
        : "r"(a[0]), "r"(a[1]), "r"(a[2]), "r"(a[3]), "r"(b[0]), "r"(b[1]));
}
__device__ __forceinline__ void ldmx4(uint32_t r[4], uint32_t addr) {
    asm volatile("ldmatrix.sync.aligned.m8n8.x4.shared.b16 {%0,%1,%2,%3}, [%4];"
        : "=r"(r[0]), "=r"(r[1]), "=r"(r[2]), "=r"(r[3]) : "r"(addr));
}
__device__ __forceinline__ float sigmoidf_(float x) {
    return __fdividef(1.0f, 1.0f + __expf(-x));
}

// ---------------------------------------------------------------------------
// k_fused: LN + left proj (recomputed per block) + t-chunk. grid (64, 8), 128 thr.
// Block (lb, jb): l = lb*8..+8, j = jb*4..+4.
// jb==0 also emits g_right; jb==1 emits cas; block (0,2) packs w_rbf^T.
// ---------------------------------------------------------------------------
__global__ __launch_bounds__(128) void k_fused(
    const float* __restrict__ xyz, const float* __restrict__ state,
    const float* __restrict__ ln_w, const float* __restrict__ ln_b,
    const float* __restrict__ w_left, const float* __restrict__ b_left,
    const float* __restrict__ w_right, const float* __restrict__ b_right,
    const float* __restrict__ w_gate, const float* __restrict__ w_rbf)
{
    __shared__ float st[8][DS];
    __shared__ float ls[8][HH];
    __shared__ float ps[128], qs[128];
    __shared__ float red[8][2];
    int lb = blockIdx.x * 8, j0 = blockIdx.y * 4;
    int tid = threadIdx.x;
    int row = tid >> 4, seg = tid & 15;

    // ---- load + partial sums (16 elems per thread) ----
    float vals[16];
    {
        const float4* src = (const float4*)(state + (lb + row) * DS + seg * 16);
        float s = 0.f, q = 0.f;
        #pragma unroll
        for (int e4 = 0; e4 < 4; e4++) {
            float4 v = src[e4];
            vals[e4 * 4] = v.x; vals[e4 * 4 + 1] = v.y;
            vals[e4 * 4 + 2] = v.z; vals[e4 * 4 + 3] = v.w;
            s += v.x + v.y + v.z + v.w;
            q += v.x * v.x + v.y * v.y + v.z * v.z + v.w * v.w;
        }
        ps[tid] = s; qs[tid] = q;
    }
    __syncthreads();
    if (tid < 8) {
        float S = 0.f, Q = 0.f;
        #pragma unroll
        for (int i = 0; i < 16; i++) { S += ps[tid * 16 + i]; Q += qs[tid * 16 + i]; }
        float mu = S * (1.0f / DS);
        red[tid][0] = mu;
        red[tid][1] = rsqrtf(Q * (1.0f / DS) - mu * mu + 1e-5f);
    }
    __syncthreads();
    {
        float mu = red[row][0], inv = red[row][1];
        const float4* lwp = (const float4*)(ln_w + seg * 16);
        const float4* lbp = (const float4*)(ln_b + seg * 16);
        #pragma unroll
        for (int e4 = 0; e4 < 4; e4++) {
            float4 lw = lwp[e4], lbv = lbp[e4];
            st[row][seg * 16 + e4 * 4]     = (vals[e4 * 4]     - mu) * inv * lw.x + lbv.x;
            st[row][seg * 16 + e4 * 4 + 1] = (vals[e4 * 4 + 1] - mu) * inv * lw.y + lbv.y;
            st[row][seg * 16 + e4 * 4 + 2] = (vals[e4 * 4 + 2] - mu) * inv * lw.z + lbv.z;
            st[row][seg * 16 + e4 * 4 + 3] = (vals[e4 * 4 + 3] - mu) * inv * lw.w + lbv.w;
        }
    }
    __syncthreads();

    // ---- left projection: thread (j = tid&31, la = tid>>5), handles la and la+4 ----
    {
        int j = tid & 31, la = tid >> 5;
        float a0 = b_left[j], a1 = a0;
        const float* s0 = st[la];
        const float* s1 = st[la + 4];
        const float* wp = w_left + j;
        #pragma unroll 8
        for (int i = 0; i < DS; i++) {
            float wv = wp[i * HH];
            a0 += s0[i] * wv;
            a1 += s1[i] * wv;
        }
        ls[la][j] = a0;
        ls[la + 4][j] = a1;
    }
    // jb==0: right projection -> g_right
    if (blockIdx.y == 0) {
        int j = tid & 31, la = tid >> 5;
        float a0 = b_right[j], a1 = a0;
        const float* s0 = st[la];
        const float* s1 = st[la + 4];
        const float* wp = w_right + j;
        #pragma unroll 8
        for (int i = 0; i < DS; i++) {
            float wv = wp[i * HH];
            a0 += s0[i] * wv;
            a1 += s1[i] * wv;
        }
        g_right[(lb + la) * HH + j] = a0;
        g_right[(lb + la + 4) * HH + j] = a1;
    }
    if (blockIdx.y == 1 && tid < 24) {
        int l8 = tid / 3, c = tid % 3;
        g_cas[(lb + l8) * 4 + c] = xyz[(lb + l8) * 9 + 3 + c];
    }
    if (blockIdx.x == 0 && blockIdx.y == 2) {
        #pragma unroll
        for (int c = 0; c < 24; c++) {
            int k0 = 2 * c, k1 = 2 * c + 1;
            float v0 = (k0 < KRBF) ? w_rbf[k0 * DP + tid] : 0.f;
            float v1 = (k1 < KRBF) ? w_rbf[k1 * DP + tid] : 0.f;
            g_wr[tid * 24 + c] = pk2(v0, v1);
        }
    }
    __syncthreads();

    // ---- t-chunk: j0..j0+3 for 8 l's, thread = p ----
    {
        int p = tid;
        float acc[8][4];
        #pragma unroll
        for (int lt = 0; lt < 8; lt++)
            #pragma unroll
            for (int qj = 0; qj < 4; qj++) acc[lt][qj] = 0.f;

        #pragma unroll 4
        for (int i = 0; i < HH; i++) {
            float wv[4];
            #pragma unroll
            for (int qj = 0; qj < 4; qj++)
                wv[qj] = w_gate[(i * HH + j0 + qj) * DP + p];
            #pragma unroll
            for (int lt = 0; lt < 8; lt++) {
                float lv = ls[lt][i];
                #pragma unroll
                for (int qj = 0; qj < 4; qj++) acc[lt][qj] += lv * wv[qj];
            }
        }
        int c0 = j0 >> 1;   // word index 0..14, 2 words per block (stride 16)
        #pragma unroll
        for (int lt = 0; lt < 8; lt++) {
            uint32_t h0 = pk2(acc[lt][0], acc[lt][1]);
            uint32_t h1 = pk2(acc[lt][2], acc[lt][3]);
            uint32_t base = (uint32_t)((lb + lt) * DP + p) * 16u + c0;
            *(uint2*)(g_tp + base) = make_uint2(h0, h1);
        }
    }
}

// ---------------------------------------------------------------------------
// k_main: mma.sync fp16 single-product. Block = (l, 64 m) x 128 p, 8 warps.
// Warp tile 32m x 32p: M0 = (wid&1)*32, P0 = (wid>>1)*32.
// A1 = right [64][80B], A2 = rbf [64][112B], B1 = t^T [128][80B],
// B2 = wrbf^T [128][112B]. Staged epilogue -> full-line STG.128.
// ---------------------------------------------------------------------------
#define A1H 0
#define A2H 5120
#define B1H 12288
#define B2H 22528
#define STG0 36864
#define STG_ROW 36
#define STG_WARP (32 * STG_ROW * 4)     // 4608 B
#define SMTOT (36864 + 8 * STG_WARP)    // 73728 B -> 2 blocks/SM

__global__ __launch_bounds__(256) void k_main(
    const float* __restrict__ b_rbf, const float* __restrict__ b_gate,
    float* __restrict__ out)
{
    extern __shared__ char smem[];
    __shared__ float dist_s[64];
    uint32_t sb = smem_u32(smem);
    int tid = threadIdx.x, lane = tid & 31, wid = tid >> 5;
    int l = blockIdx.x, mb = blockIdx.y * 64;

    if (tid < 64) {
        int m = mb + tid;
        float dx = g_cas[m * 4]     - g_cas[l * 4];
        float dy = g_cas[m * 4 + 1] - g_cas[l * 4 + 1];
        float dz = g_cas[m * 4 + 2] - g_cas[l * 4 + 2];
        dist_s[tid] = sqrtf(fmaxf(dx * dx + dy * dy + dz * dz, 1e-12f));
    }

    // A1 fill: right -> fp16 [64][80B]
    {
        int row = tid >> 2, ch = tid & 3;
        const float4* src = (const float4*)(g_right + (mb + row) * HH + ch * 8);
        float4 x = src[0], y = src[1];
        uint4 h = make_uint4(pk2(x.x, x.y), pk2(x.z, x.w), pk2(y.x, y.y), pk2(y.z, y.w));
        *(uint4*)(smem + A1H + row * 80 + ch * 16) = h;
    }
    // B1 fill: t^T [128][80B], 16 words (64B) data per row, 4 chunks of 16B
    #pragma unroll
    for (int it = 0; it < 2; it++) {
        int idx = it * 256 + tid;
        int row = idx >> 2, ch = idx & 3;
        uint32_t gb = (uint32_t)(l * DP + row) * 16u + ch * 4;
        *(uint4*)(smem + B1H + row * 80 + ch * 16) = *(const uint4*)(g_tp + gb);
    }
    // B2 fill: w_rbf^T [128][112B] (768 chunks)
    #pragma unroll
    for (int it = 0; it < 3; it++) {
        int idx = it * 256 + tid;
        int row = idx / 6, ch = idx - row * 6;
        *(uint4*)(smem + B2H + row * 112 + ch * 16) = *(const uint4*)(g_wr + row * 24 + ch * 4);
    }
    __syncthreads();

    // A2 fill: rbf features fp16 [64][112B]
    {
        int m = tid >> 2, kg = tid & 3;
        float dist = dist_s[m];
        const float DMU = 20.0f / 35.0f, INV_SIG = 36.0f / 20.0f;
        #pragma unroll
        for (int kk = 0; kk < 6; kk++) {
            int k = kg * 12 + 2 * kk;
            float e0 = 0.f, e1 = 0.f;
            if (k < KRBF) {
                float u = (dist - (2.0f + (float)k * DMU)) * INV_SIG;
                e0 = __expf(-u * u);
            }
            if (k + 1 < KRBF) {
                float u = (dist - (2.0f + (float)(k + 1) * DMU)) * INV_SIG;
                e1 = __expf(-u * u);
            }
            *(uint32_t*)(smem + A2H + m * 112 + k * 2) = pk2(e0, e1);
        }
    }
    __syncthreads();

    // ---- ldmatrix address components ----
    uint32_t rr = lane & 7, q = lane >> 3;
    uint32_t a_r = (q & 1) << 3, a_k = (q >> 1) << 3;
    uint32_t b_r = (q >> 1) << 3, b_k = (q & 1) << 3;
    int M0 = (wid & 1) * 32, P0 = (wid >> 1) * 32;

    // ---- pass 1: logits (K=32, 2 ks) ----
    uint32_t Ah[2][2][4];
    #pragma unroll
    for (int mt = 0; mt < 2; mt++)
        #pragma unroll
        for (int ks = 0; ks < 2; ks++)
            ldmx4(Ah[mt][ks], sb + A1H + (M0 + mt * 16 + rr + a_r) * 80 + (ks * 16 + a_k) * 2);

    float accL[2][4][4];
    #pragma unroll
    for (int mt = 0; mt < 2; mt++)
        #pragma unroll
        for (int nt = 0; nt < 4; nt++)
            #pragma unroll
            for (int j = 0; j < 4; j++) accL[mt][nt][j] = 0.f;

    #pragma unroll
    for (int npp = 0; npp < 2; npp++) {
        int n0 = P0 + npp * 16;
        uint32_t bbase = sb + B1H + (n0 + rr + b_r) * 80 + b_k * 2;
        #pragma unroll
        for (int ks = 0; ks < 2; ks++) {
            uint32_t bh[4];
            ldmx4(bh, bbase + ks * 32);
            #pragma unroll
            for (int mt = 0; mt < 2; mt++) {
                mma16816(accL[mt][2 * npp],     Ah[mt][ks], bh);
                mma16816(accL[mt][2 * npp + 1], Ah[mt][ks], bh + 2);
            }
        }
    }

    // ---- pass 2: feat (K=48, 3 ks) + epilogue into staging ----
    uint32_t Fh[2][3][4];
    #pragma unroll
    for (int mt = 0; mt < 2; mt++)
        #pragma unroll
        for (int ks = 0; ks < 3; ks++)
            ldmx4(Fh[mt][ks], sb + A2H + (M0 + mt * 16 + rr + a_r) * 112 + (ks * 16 + a_k) * 2);

    int r0 = lane >> 2, c2 = (lane & 3) * 2;
    float* stg = (float*)(smem + STG0 + wid * STG_WARP);

    #pragma unroll
    for (int npp = 0; npp < 2; npp++) {
        int n0 = P0 + npp * 16;
        uint32_t bbase = sb + B2H + (n0 + rr + b_r) * 112 + b_k * 2;
        float accF[2][2][4];
        #pragma unroll
        for (int mt = 0; mt < 2; mt++)
            #pragma unroll
            for (int nt = 0; nt < 2; nt++)
                #pragma unroll
                for (int j = 0; j < 4; j++) accF[mt][nt][j] = 0.f;
        #pragma unroll
        for (int ks = 0; ks < 3; ks++) {
            uint32_t bh[4];
            ldmx4(bh, bbase + ks * 32);
            #pragma unroll
            for (int mt = 0; mt < 2; mt++) {
                mma16816(accF[mt][0], Fh[mt][ks], bh);
                mma16816(accF[mt][1], Fh[mt][ks], bh + 2);
            }
        }
        // epilogue -> per-warp staging smem
        #pragma unroll
        for (int mt = 0; mt < 2; mt++) {
            #pragma unroll
            for (int ntl = 0; ntl < 2; ntl++) {
                int pl = npp * 16 + ntl * 8 + c2;
                int pg = P0 + pl;
                float2 bg = *(const float2*)(b_gate + pg);
                float2 br = *(const float2*)(b_rbf + pg);
                const float* Lc = accL[mt][2 * npp + ntl];
                const float* Fc = accF[mt][ntl];
                int ra = mt * 16 + r0;
                float2 v0, v1;
                v0.x = (Fc[0] + br.x) * sigmoidf_(Lc[0] + bg.x);
                v0.y = (Fc[1] + br.y) * sigmoidf_(Lc[1] + bg.y);
                v1.x = (Fc[2] + br.x) * sigmoidf_(Lc[2] + bg.x);
                v1.y = (Fc[3] + br.y) * sigmoidf_(Lc[3] + bg.y);
                *(float2*)(stg + ra * STG_ROW + pl) = v0;
                *(float2*)(stg + (ra + 8) * STG_ROW + pl) = v1;
            }
        }
    }
    __syncwarp();

    // ---- drain: 4 rows per STG.128, full 128B lines ----
    {
        int c4 = lane & 7, rq = lane >> 3;
        #pragma unroll
        for (int it = 0; it < 8; it++) {
            int rs = it * 4 + rq;
            float4 vv = *(const float4*)(stg + rs * STG_ROW + c4 * 4);
            int m = mb + M0 + rs;
            *(float4*)(out + ((size_t)l * LL + m) * DP + P0 + c4 * 4) = vv;
        }
    }
}

// ---------------------------------------------------------------------------
extern "C" void kernel_launch(void* const* d_in, const int* in_sizes, int n_in,
                              void* d_out, int out_size)
{
    const float* xyz     = (const float*)d_in[0];
    const float* state   = (const float*)d_in[1];
    const float* ln_w    = (const float*)d_in[2];
    const float* ln_b    = (const float*)d_in[3];
    const float* w_rbf   = (const float*)d_in[4];
    const float* b_rbf   = (const float*)d_in[5];
    const float* w_left  = (const float*)d_in[6];
    const float* b_left  = (const float*)d_in[7];
    const float* w_right = (const float*)d_in[8];
    const float* b_right = (const float*)d_in[9];
    const float* w_gate  = (const float*)d_in[10];
    const float* b_gate  = (const float*)d_in[11];
    float* out = (float*)d_out;

    k_fused<<<dim3(64, 8), 128>>>(xyz, state, ln_w, ln_b, w_left, b_left,
                                  w_right, b_right, w_gate, w_rbf);

    cudaFuncSetAttribute(k_main, cudaFuncAttributeMaxDynamicSharedMemorySize, SMTOT);
    k_main<<<dim3(LL, 8), 256, SMTOT>>>(b_rbf, b_gate, out);
}

// round 12
// speedup vs baseline: 1.3740x; 1.2224x over previous
#include <cuda_runtime.h>
#include <cuda_fp16.h>
#include <math.h>
#include <stdint.h>

#define LL 512
#define DS 256
#define HH 32
#define DP 128
#define KRBF 36

// ---------------- scratch globals ----------------
__device__ float    g_left[LL * HH];
__device__ float    g_right[LL * HH];      // [m][32] fp32
__device__ float    g_cas[LL * 4];
__device__ uint32_t g_tp[LL * DP * 16];    // t^T fp16: [l][p][16 words = 32 k]
__device__ uint32_t g_wr[DP * 24];         // w_rbf^T fp16: [p][24 words = 48 k]

// ---------------- helpers ----------------
__device__ __forceinline__ uint32_t smem_u32(const void* p) {
    uint32_t a;
    asm("{ .reg .u64 t; cvta.to.shared.u64 t, %1; cvt.u32.u64 %0, t; }" : "=r"(a) : "l"(p));
    return a;
}
__device__ __forceinline__ uint32_t pk2(float a, float b) {
    __half2 h = __floats2half2_rn(a, b);
    return *(uint32_t*)&h;
}
__device__ __forceinline__ void mma16816(float d[4], const uint32_t a[4], const uint32_t b[2]) {
    asm volatile("mma.sync.aligned.m16n8k16.row.col.f32.f16.f16.f32 "
        "{%0,%1,%2,%3}, {%4,%5,%6,%7}, {%8,%9}, {%0,%1,%2,%3};"
        : "+f"(d[0]), "+f"(d[1]), "+f"(d[2]), "+f"(d[3])
        : "r"(a[0]), "r"(a[1]), "r"(a[2]), "r"(a[3]), "r"(b[0]), "r"(b[1]));
}
__device__ __forceinline__ void ldmx4(uint32_t r[4], uint32_t addr) {
    asm volatile("ldmatrix.sync.aligned.m8n8.x4.shared.b16 {%0,%1,%2,%3}, [%4];"
        : "=r"(r[0]), "=r"(r[1]), "=r"(r[2]), "=r"(r[3]) : "r"(addr));
}
__device__ __forceinline__ float sigmoid_t(float x) {
    float t;
    asm("tanh.approx.f32 %0, %1;" : "=f"(t) : "f"(0.5f * x));
    return fmaf(0.5f, t, 0.5f);
}

// ---------------------------------------------------------------------------
// k_prep (R4 proven): LayerNorm + left/right projections + cas; block 0 packs w_rbf^T
// grid = 512, 256 threads
// ---------------------------------------------------------------------------
__global__ __launch_bounds__(256) void k_prep(
    const float* __restrict__ xyz, const float* __restrict__ state,
    const float* __restrict__ ln_w, const float* __restrict__ ln_b,
    const float* __restrict__ w_left, const float* __restrict__ b_left,
    const float* __restrict__ w_right, const float* __restrict__ b_right,
    const float* __restrict__ w_rbf)
{
    int l = blockIdx.x, tid = threadIdx.x;
    __shared__ float st_s[DS];
    __shared__ float red[18];
    __shared__ float part[64][4];

    float x = state[l * DS + tid];
    float s = x, q = x * x;
    #pragma unroll
    for (int o = 16; o; o >>= 1) {
        s += __shfl_xor_sync(0xFFFFFFFFu, s, o);
        q += __shfl_xor_sync(0xFFFFFFFFu, q, o);
    }
    int wid = tid >> 5, lane = tid & 31;
    if (lane == 0) { red[wid] = s; red[8 + wid] = q; }
    __syncthreads();
    if (tid == 0) {
        float S = 0.f, Q = 0.f;
        #pragma unroll
        for (int i = 0; i < 8; i++) { S += red[i]; Q += red[8 + i]; }
        float mu = S * (1.0f / DS);
        float var = Q * (1.0f / DS) - mu * mu;
        red[16] = mu; red[17] = rsqrtf(var + 1e-5f);
    }
    __syncthreads();
    st_s[tid] = (x - red[16]) * red[17] * ln_w[tid] + ln_b[tid];
    __syncthreads();

    {
        int j = tid & 31, half = (tid >> 5) & 1, seg = tid >> 6;
        const float* w = half ? w_right : w_left;
        float acc = 0.f;
        int i0 = seg * 64;
        #pragma unroll 8
        for (int i = 0; i < 64; i++) acc += st_s[i0 + i] * w[(i0 + i) * HH + j];
        part[half * 32 + j][seg] = acc;
    }
    __syncthreads();
    if (tid < 64) {
        int j = tid & 31, half = tid >> 5;
        float a = part[tid][0] + part[tid][1] + part[tid][2] + part[tid][3]
                + (half ? b_right[j] : b_left[j]);
        if (half) g_right[l * HH + j] = a;
        else      g_left[l * HH + j] = a;
    }
    if (tid < 3) g_cas[l * 4 + tid] = xyz[l * 9 + 3 + tid];

    if (blockIdx.x == 0 && tid < DP) {
        #pragma unroll
        for (int c = 0; c < 24; c++) {
            int k0 = 2 * c, k1 = 2 * c + 1;
            float v0 = (k0 < KRBF) ? w_rbf[k0 * DP + tid] : 0.f;
            float v1 = (k1 < KRBF) ? w_rbf[k1 * DP + tid] : 0.f;
            g_wr[tid * 24 + c] = pk2(v0, v1);
        }
    }
}

// ---------------------------------------------------------------------------
// k_t: t[l,k,p] = sum_i left[l,i]*Wg[i,k,p]; emit t^T fp16 [l][p][k], stride 16
// grid = (64 lb, 8 jb): 8 l x 4 j x 128 p per block, 128 threads
// ---------------------------------------------------------------------------
__global__ __launch_bounds__(128) void k_t(const float* __restrict__ w_gate)
{
    __shared__ float ls[8 * HH];
    int lb = blockIdx.x * 8, j0 = blockIdx.y * 4, p = threadIdx.x;
    for (int i = p; i < 8 * HH; i += 128) ls[i] = g_left[lb * HH + i];
    __syncthreads();

    float acc[8][4];
    #pragma unroll
    for (int lt = 0; lt < 8; lt++)
        #pragma unroll
        for (int qj = 0; qj < 4; qj++) acc[lt][qj] = 0.f;

    #pragma unroll 4
    for (int i = 0; i < HH; i++) {
        float wv[4];
        #pragma unroll
        for (int qj = 0; qj < 4; qj++)
            wv[qj] = w_gate[(i * HH + j0 + qj) * DP + p];
        #pragma unroll
        for (int lt = 0; lt < 8; lt++) {
            float lv = ls[lt * HH + i];
            #pragma unroll
            for (int qj = 0; qj < 4; qj++) acc[lt][qj] += lv * wv[qj];
        }
    }
    int c0 = j0 >> 1;   // word index 0..14, 2 words per block
    #pragma unroll
    for (int lt = 0; lt < 8; lt++) {
        uint32_t h0 = pk2(acc[lt][0], acc[lt][1]);
        uint32_t h1 = pk2(acc[lt][2], acc[lt][3]);
        uint32_t base = (uint32_t)((lb + lt) * DP + p) * 16u + c0;
        *(uint2*)(g_tp + base) = make_uint2(h0, h1);
    }
}

// ---------------------------------------------------------------------------
// k_main: mma.sync fp16 single-product, 3 blocks/SM target.
// Block = (l, 64 m) x 128 p, 8 warps; warp tile 32m x 32p.
// Early sigmoid after pass 1 (tanh.approx), gate kept as half2 (reg savings).
// Direct float2 stores. smem 36864 B.
// ---------------------------------------------------------------------------
#define A1H 0
#define A2H 5120
#define B1H 12288
#define B2H 22528
#define SMTOT 36864

__global__ __launch_bounds__(256, 3) void k_main(
    const float* __restrict__ b_rbf, const float* __restrict__ b_gate,
    float* __restrict__ out)
{
    extern __shared__ char smem[];
    __shared__ float dist_s[64];
    uint32_t sb = smem_u32(smem);
    int tid = threadIdx.x, lane = tid & 31, wid = tid >> 5;
    int l = blockIdx.x, mb = blockIdx.y * 64;

    if (tid < 64) {
        int m = mb + tid;
        float dx = g_cas[m * 4]     - g_cas[l * 4];
        float dy = g_cas[m * 4 + 1] - g_cas[l * 4 + 1];
        float dz = g_cas[m * 4 + 2] - g_cas[l * 4 + 2];
        dist_s[tid] = sqrtf(fmaxf(dx * dx + dy * dy + dz * dz, 1e-12f));
    }

    // A1 fill: right -> fp16 [64][80B]
    {
        int row = tid >> 2, ch = tid & 3;
        const float4* src = (const float4*)(g_right + (mb + row) * HH + ch * 8);
        float4 x = src[0], y = src[1];
        uint4 h = make_uint4(pk2(x.x, x.y), pk2(x.z, x.w), pk2(y.x, y.y), pk2(y.z, y.w));
        *(uint4*)(smem + A1H + row * 80 + ch * 16) = h;
    }
    // B1 fill: t^T [128][80B], 4 chunks of 16B per row
    #pragma unroll
    for (int it = 0; it < 2; it++) {
        int idx = it * 256 + tid;
        int row = idx >> 2, ch = idx & 3;
        uint32_t gb = (uint32_t)(l * DP + row) * 16u + ch * 4;
        *(uint4*)(smem + B1H + row * 80 + ch * 16) = *(const uint4*)(g_tp + gb);
    }
    // B2 fill: w_rbf^T [128][112B]
    #pragma unroll
    for (int it = 0; it < 3; it++) {
        int idx = it * 256 + tid;
        int row = idx / 6, ch = idx - row * 6;
        *(uint4*)(smem + B2H + row * 112 + ch * 16) = *(const uint4*)(g_wr + row * 24 + ch * 4);
    }
    __syncthreads();

    // A2 fill: rbf features fp16 [64][112B]
    {
        int m = tid >> 2, kg = tid & 3;
        float dist = dist_s[m];
        const float DMU = 20.0f / 35.0f, INV_SIG = 36.0f / 20.0f;
        #pragma unroll
        for (int kk = 0; kk < 6; kk++) {
            int k = kg * 12 + 2 * kk;
            float e0 = 0.f, e1 = 0.f;
            if (k < KRBF) {
                float u = (dist - (2.0f + (float)k * DMU)) * INV_SIG;
                e0 = __expf(-u * u);
            }
            if (k + 1 < KRBF) {
                float u = (dist - (2.0f + (float)(k + 1) * DMU)) * INV_SIG;
                e1 = __expf(-u * u);
            }
            *(uint32_t*)(smem + A2H + m * 112 + k * 2) = pk2(e0, e1);
        }
    }
    __syncthreads();

    // ---- ldmatrix address components ----
    uint32_t rr = lane & 7, q = lane >> 3;
    uint32_t a_r = (q & 1) << 3, a_k = (q >> 1) << 3;
    uint32_t b_r = (q >> 1) << 3, b_k = (q & 1) << 3;
    int M0 = (wid & 1) * 32, P0 = (wid >> 1) * 32;
    int r0 = lane >> 2, c2 = (lane & 3) * 2;

    // ---- pass 1: logits (K=32, 2 ks) ----
    uint32_t Ah[2][2][4];
    #pragma unroll
    for (int mt = 0; mt < 2; mt++)
        #pragma unroll
        for (int ks = 0; ks < 2; ks++)
            ldmx4(Ah[mt][ks], sb + A1H + (M0 + mt * 16 + rr + a_r) * 80 + (ks * 16 + a_k) * 2);

    float accL[2][4][4];
    #pragma unroll
    for (int mt = 0; mt < 2; mt++)
        #pragma unroll
        for (int nt = 0; nt < 4; nt++)
            #pragma unroll
            for (int j = 0; j < 4; j++) accL[mt][nt][j] = 0.f;

    #pragma unroll
    for (int npp = 0; npp < 2; npp++) {
        int n0 = P0 + npp * 16;
        uint32_t bbase = sb + B1H + (n0 + rr + b_r) * 80 + b_k * 2;
        #pragma unroll
        for (int ks = 0; ks < 2; ks++) {
            uint32_t bh[4];
            ldmx4(bh, bbase + ks * 32);
            #pragma unroll
            for (int mt = 0; mt < 2; mt++) {
                mma16816(accL[mt][2 * npp],     Ah[mt][ks], bh);
                mma16816(accL[mt][2 * npp + 1], Ah[mt][ks], bh + 2);
            }
        }
    }

    // ---- early sigmoid: gate packed half2 [mt][nt][2] ----
    uint32_t gate[2][4][2];
    #pragma unroll
    for (int nt = 0; nt < 4; nt++) {
        int pg = P0 + nt * 8 + c2;
        float2 bg = *(const float2*)(b_gate + pg);
        #pragma unroll
        for (int mt = 0; mt < 2; mt++) {
            gate[mt][nt][0] = pk2(sigmoid_t(accL[mt][nt][0] + bg.x),
                                  sigmoid_t(accL[mt][nt][1] + bg.y));
            gate[mt][nt][1] = pk2(sigmoid_t(accL[mt][nt][2] + bg.x),
                                  sigmoid_t(accL[mt][nt][3] + bg.y));
        }
    }

    // ---- pass 2: feat (K=48, 3 ks) + fused epilogue, direct stores ----
    uint32_t Fh[2][3][4];
    #pragma unroll
    for (int mt = 0; mt < 2; mt++)
        #pragma unroll
        for (int ks = 0; ks < 3; ks++)
            ldmx4(Fh[mt][ks], sb + A2H + (M0 + mt * 16 + rr + a_r) * 112 + (ks * 16 + a_k) * 2);

    #pragma unroll
    for (int npp = 0; npp < 2; npp++) {
        int n0 = P0 + npp * 16;
        uint32_t bbase = sb + B2H + (n0 + rr + b_r) * 112 + b_k * 2;
        float accF[2][2][4];
        #pragma unroll
        for (int mt = 0; mt < 2; mt++)
            #pragma unroll
            for (int nt = 0; nt < 2; nt++)
                #pragma unroll
                for (int j = 0; j < 4; j++) accF[mt][nt][j] = 0.f;
        #pragma unroll
        for (int ks = 0; ks < 3; ks++) {
            uint32_t bh[4];
            ldmx4(bh, bbase + ks * 32);
            #pragma unroll
            for (int mt = 0; mt < 2; mt++) {
                mma16816(accF[mt][0], Fh[mt][ks], bh);
                mma16816(accF[mt][1], Fh[mt][ks], bh + 2);
            }
        }
        // epilogue: feat * gate -> direct float2 stores
        #pragma unroll
        for (int mt = 0; mt < 2; mt++) {
            #pragma unroll
            for (int ntl = 0; ntl < 2; ntl++) {
                int nt = 2 * npp + ntl;
                int pg = P0 + nt * 8 + c2;
                float2 br = *(const float2*)(b_rbf + pg);
                const float* Fc = accF[mt][ntl];
                float2 g0 = __half22float2(*(const __half2*)&gate[mt][nt][0]);
                float2 g1 = __half22float2(*(const __half2*)&gate[mt][nt][1]);
                int m0 = mb + M0 + mt * 16 + r0;
                float* o0 = out + ((size_t)l * LL + m0) * DP + pg;
                float2 v0, v1;
                v0.x = (Fc[0] + br.x) * g0.x;
                v0.y = (Fc[1] + br.y) * g0.y;
                v1.x = (Fc[2] + br.x) * g1.x;
                v1.y = (Fc[3] + br.y) * g1.y;
                *(float2*)o0 = v0;
                *(float2*)(o0 + 8 * DP) = v1;
            }
        }
    }
}

// ---------------------------------------------------------------------------
extern "C" void kernel_launch(void* const* d_in, const int* in_sizes, int n_in,
                              void* d_out, int out_size)
{
    const float* xyz     = (const float*)d_in[0];
    const float* state   = (const float*)d_in[1];
    const float* ln_w    = (const float*)d_in[2];
    const float* ln_b    = (const float*)d_in[3];
    const float* w_rbf   = (const float*)d_in[4];
    const float* b_rbf   = (const float*)d_in[5];
    const float* w_left  = (const float*)d_in[6];
    const float* b_left  = (const float*)d_in[7];
    const float* w_right = (const float*)d_in[8];
    const float* b_right = (const float*)d_in[9];
    const float* w_gate  = (const float*)d_in[10];
    const float* b_gate  = (const float*)d_in[11];
    float* out = (float*)d_out;

    k_prep<<<LL, 256>>>(xyz, state, ln_w, ln_b, w_left, b_left, w_right, b_right, w_rbf);
    k_t<<<dim3(64, 8), 128>>>(w_gate);

    cudaFuncSetAttribute(k_main, cudaFuncAttributeMaxDynamicSharedMemorySize, SMTOT);
    k_main<<<dim3(LL, 8), 256, SMTOT>>>(b_rbf, b_gate, out);
}